// round 5
// baseline (speedup 1.0000x reference)
#include <cuda_runtime.h>
#include <cmath>

#define NMAX 100000
#define FDIM 128

// Scratch (device globals: allocation-free per harness rules)
__device__ int   g_is64;                      // 1 if edge_index is int64, 0 if int32
__device__ float g_deg[NMAX];
__device__ float g_dinv[NMAX];
__device__ float g_y[(size_t)NMAX * FDIM];    // (X@W) * dinv[row]
__device__ float g_agg[(size_t)NMAX * FDIM];  // aggregation accumulator

// ---------------------------------------------------------------------------
// index dtype detection + loading
// ---------------------------------------------------------------------------
__global__ void detect_init_kernel() { g_is64 = 1; }

// Read first E words as int64. True int64 data: all values in [0, N).
// int32 data read as int64: high word is another random index -> value >= 2^32.
__global__ void detect_kernel(const unsigned long long* __restrict__ ei,
                              int E, unsigned long long n) {
    int i = blockIdx.x * blockDim.x + threadIdx.x;
    if (i < E) {
        if (ei[i] >= n) g_is64 = 0;   // racy but monotonic: only ever 1 -> 0
    }
}

// idx i in [0, 2E): i < E -> src row, else dst row
__device__ __forceinline__ int load_idx(const void* ei, int i) {
    if (g_is64) return (int)((const long long*)ei)[i];
    return ((const int*)ei)[i];
}

// ---------------------------------------------------------------------------
// degree / normalization
// ---------------------------------------------------------------------------
__global__ void deg_init_kernel(int n) {
    int i = blockIdx.x * blockDim.x + threadIdx.x;
    if (i < n) g_deg[i] = 1.0f;  // self loop
}

__global__ void deg_accum_kernel(const void* __restrict__ ei, int E, int n) {
    int e = blockIdx.x * blockDim.x + threadIdx.x;
    if (e < E) {
        int d = load_idx(ei, E + e);  // dst row
        if (d >= 0 && d < n) atomicAdd(&g_deg[d], 1.0f);
    }
}

__global__ void dinv_kernel(int n) {
    int i = blockIdx.x * blockDim.x + threadIdx.x;
    if (i < n) g_dinv[i] = rsqrtf(g_deg[i]);
}

// ---------------------------------------------------------------------------
// GEMM: out_row = (act(A_row) @ W) * dinv[row]; writes g_y and g_agg (=self loop)
// LAYER==1: A = X (identity activation)
// LAYER==2: A = g_agg (raw layer-1 aggregate), act = relu(a*dinv[row] + b1[k])
//   Safe self-overwrite: BN=128 covers all cols, so each row is read+written by
//   exactly ONE block, all reads (k-loop) strictly before all writes (epilogue).
// ---------------------------------------------------------------------------
template <int LAYER>
__global__ void __launch_bounds__(256)
gemm_scale_kernel(const float* __restrict__ X,
                  const float* __restrict__ W,
                  const float* __restrict__ bin,   // b1 for LAYER==2 activation
                  int M) {
    constexpr int BK = 8;
    __shared__ float As[BK][128];   // transposed A tile
    __shared__ float Bs[BK][128];

    const int tid = threadIdx.x;
    const int block_row = blockIdx.x * 128;
    const int tc = (tid % 16) * 8;       // output col base for this thread
    const int tr = (tid / 16) * 8;       // output row base (within tile)

    // A tile load mapping: 128 rows x 8 k = 256 float4 (one per thread)
    const int a_row = tid >> 1;
    const int a_c4  = (tid & 1) * 4;
    // B tile load mapping: 8 k x 128 n = 256 float4
    const int b_k   = tid >> 5;
    const int b_c4  = (tid & 31) * 4;

    const int ga_row = block_row + a_row;
    float dva = 0.0f;
    if (LAYER == 2 && ga_row < M) dva = g_dinv[ga_row];

    const float* Aptr = (LAYER == 1) ? X : (const float*)g_agg;

    float acc[8][8];
#pragma unroll
    for (int i = 0; i < 8; i++)
#pragma unroll
        for (int j = 0; j < 8; j++) acc[i][j] = 0.0f;

    for (int k0 = 0; k0 < FDIM; k0 += BK) {
        float4 av = make_float4(0.f, 0.f, 0.f, 0.f);
        if (ga_row < M)
            av = *reinterpret_cast<const float4*>(Aptr + (size_t)ga_row * FDIM + k0 + a_c4);
        if (LAYER == 2) {
            av.x = fmaxf(fmaf(av.x, dva, bin[k0 + a_c4 + 0]), 0.0f);
            av.y = fmaxf(fmaf(av.y, dva, bin[k0 + a_c4 + 1]), 0.0f);
            av.z = fmaxf(fmaf(av.z, dva, bin[k0 + a_c4 + 2]), 0.0f);
            av.w = fmaxf(fmaf(av.w, dva, bin[k0 + a_c4 + 3]), 0.0f);
        }
        As[a_c4 + 0][a_row] = av.x;
        As[a_c4 + 1][a_row] = av.y;
        As[a_c4 + 2][a_row] = av.z;
        As[a_c4 + 3][a_row] = av.w;

        *reinterpret_cast<float4*>(&Bs[b_k][b_c4]) =
            *reinterpret_cast<const float4*>(W + (size_t)(k0 + b_k) * FDIM + b_c4);

        __syncthreads();

#pragma unroll
        for (int k = 0; k < BK; k++) {
            float rm[8], rn[8];
#pragma unroll
            for (int i = 0; i < 8; i++) rm[i] = As[k][tr + i];
#pragma unroll
            for (int j = 0; j < 8; j++) rn[j] = Bs[k][tc + j];
#pragma unroll
            for (int i = 0; i < 8; i++)
#pragma unroll
                for (int j = 0; j < 8; j++) acc[i][j] = fmaf(rm[i], rn[j], acc[i][j]);
        }
        __syncthreads();
    }

    // epilogue: y = acc * dinv[row]; agg initialized with self-loop term (= y)
#pragma unroll
    for (int i = 0; i < 8; i++) {
        int r = block_row + tr + i;
        if (r < M) {
            float dv = g_dinv[r];
#pragma unroll
            for (int j = 0; j < 8; j += 4) {
                float4 v;
                v.x = acc[i][j + 0] * dv;
                v.y = acc[i][j + 1] * dv;
                v.z = acc[i][j + 2] * dv;
                v.w = acc[i][j + 3] * dv;
                *reinterpret_cast<float4*>(g_y + (size_t)r * FDIM + tc + j) = v;
                *reinterpret_cast<float4*>(g_agg + (size_t)r * FDIM + tc + j) = v;
            }
        }
    }
}

// ---------------------------------------------------------------------------
// scatter-add: one warp per edge; lane handles 4 consecutive floats.
// atomicAdd with unused return compiles to REDG.ADD.F32 (no-return L2 red).
// ---------------------------------------------------------------------------
__global__ void __launch_bounds__(256)
scatter_kernel(const void* __restrict__ ei, int E, int n) {
    int gw = (int)((blockIdx.x * blockDim.x + threadIdx.x) >> 5);
    int lane = threadIdx.x & 31;
    if (gw >= E) return;
    int s = 0, d = 0;
    if (lane == 0) {
        s = load_idx(ei, gw);        // src row
        d = load_idx(ei, E + gw);    // dst row
    }
    s = __shfl_sync(0xffffffffu, s, 0);
    d = __shfl_sync(0xffffffffu, d, 0);
    if ((unsigned)s >= (unsigned)n || (unsigned)d >= (unsigned)n) return;
    float4 v = *reinterpret_cast<const float4*>(g_y + (size_t)s * FDIM + lane * 4);
    float* p = g_agg + (size_t)d * FDIM + lane * 4;
    atomicAdd(p + 0, v.x);
    atomicAdd(p + 1, v.y);
    atomicAdd(p + 2, v.z);
    atomicAdd(p + 3, v.w);
}

// ---------------------------------------------------------------------------
// final epilogue: out = sigmoid(agg2*dinv + b2); cols >= 123 forced to 0.7
// ---------------------------------------------------------------------------
__global__ void epilogue2_kernel(const float* __restrict__ b2,
                                 float* __restrict__ out, int M) {
    int i4 = blockIdx.x * blockDim.x + threadIdx.x;  // over M*32 float4s
    if (i4 >= M * 32) return;
    int r = i4 >> 5;
    int c4 = (i4 & 31) * 4;
    float dv = g_dinv[r];
    const float4 a = *reinterpret_cast<const float4*>(g_agg + (size_t)r * FDIM + c4);
    float4 o;
    float t;
    t = fmaf(a.x, dv, b2[c4 + 0]); o.x = 1.0f / (1.0f + expf(-t));
    t = fmaf(a.y, dv, b2[c4 + 1]); o.y = 1.0f / (1.0f + expf(-t));
    t = fmaf(a.z, dv, b2[c4 + 2]); o.z = 1.0f / (1.0f + expf(-t));
    t = fmaf(a.w, dv, b2[c4 + 3]); o.w = 1.0f / (1.0f + expf(-t));
    if (c4 + 0 >= 123) o.x = 0.7f;
    if (c4 + 1 >= 123) o.y = 0.7f;
    if (c4 + 2 >= 123) o.z = 0.7f;
    if (c4 + 3 >= 123) o.w = 0.7f;
    *reinterpret_cast<float4*>(out + (size_t)r * FDIM + c4) = o;
}

// ---------------------------------------------------------------------------
extern "C" void kernel_launch(void* const* d_in, const int* in_sizes, int n_in,
                              void* d_out, int out_size) {
    const float* x  = (const float*)d_in[0];
    const void*  ei = d_in[1];
    const float* W1 = (const float*)d_in[2];
    const float* b1 = (const float*)d_in[3];
    const float* W2 = (const float*)d_in[4];
    const float* b2 = (const float*)d_in[5];
    float* out      = (float*)d_out;

    const int N = in_sizes[0] / FDIM;
    const int E = in_sizes[1] / 2;

    // detect index dtype (reads first E int64 words: in-bounds for both dtypes)
    detect_init_kernel<<<1, 1>>>();
    detect_kernel<<<(E + 255) / 256, 256>>>(
        (const unsigned long long*)ei, E, (unsigned long long)N);

    // degree + normalization
    deg_init_kernel<<<(N + 255) / 256, 256>>>(N);
    deg_accum_kernel<<<(E + 255) / 256, 256>>>(ei, E, N);
    dinv_kernel<<<(N + 255) / 256, 256>>>(N);

    const int gemm_blocks = (N + 127) / 128;
    const int scat_blocks = (E + 7) / 8;  // 8 warps/block, 1 warp per edge

    // layer 1: y1 = (x@W1)*dinv, agg1 = y1 (+self loop) then edge scatter
    gemm_scale_kernel<1><<<gemm_blocks, 256>>>(x, W1, nullptr, N);
    scatter_kernel<<<scat_blocks, 256>>>(ei, E, N);

    // layer 2: h = relu(agg1*dinv + b1) fused into A load; y2/agg2 written
    gemm_scale_kernel<2><<<gemm_blocks, 256>>>(nullptr, W2, b1, N);
    scatter_kernel<<<scat_blocks, 256>>>(ei, E, N);

    // sigmoid + owner-id columns
    epilogue2_kernel<<<(N * 32 + 255) / 256, 256>>>(b2, out, N);
}

// round 7
// speedup vs baseline: 2.3047x; 2.3047x over previous
#include <cuda_runtime.h>
#include <cmath>

#define NMAX 100000
#define EMAX 1600000
#define FDIM 128

// Scratch (device globals: allocation-free per harness rules)
__device__ int   g_is64;                      // 1 if edge_index is int64, 0 if int32
__device__ int   g_cnt[NMAX];                 // incoming-edge counts
__device__ int   g_off[NMAX + 1];             // CSR offsets (by dst)
__device__ int   g_cur[NMAX];                 // placement cursors
__device__ int   g_eidx[EMAX];                // src node per CSR slot
__device__ float g_dinv[NMAX];
__device__ float g_y[(size_t)NMAX * FDIM];    // (act(A)@W) * dinv[row]
__device__ float g_agg[(size_t)NMAX * FDIM];  // aggregation result (layer 1)

// ---------------------------------------------------------------------------
// index dtype detection + loading
// ---------------------------------------------------------------------------
__global__ void detect_init_kernel() { g_is64 = 1; }

// Read first E words as int64. True int64 data: all values in [0, N).
// int32 data read as int64: high word is another random index -> >= 2^32.
__global__ void detect_kernel(const unsigned long long* __restrict__ ei,
                              int E, unsigned long long n) {
    int i = blockIdx.x * blockDim.x + threadIdx.x;
    if (i < E) {
        if (ei[i] >= n) g_is64 = 0;   // racy but monotonic: only ever 1 -> 0
    }
}

// idx i in [0, 2E): i < E -> src row, else dst row
__device__ __forceinline__ int load_idx(const void* ei, int i) {
    if (g_is64) return (int)((const long long*)ei)[i];
    return ((const int*)ei)[i];
}

// ---------------------------------------------------------------------------
// CSR build: histogram -> scan -> place
// ---------------------------------------------------------------------------
__global__ void cnt_init_kernel(int n) {
    int i = blockIdx.x * blockDim.x + threadIdx.x;
    if (i < n) g_cnt[i] = 0;
}

__global__ void cnt_accum_kernel(const void* __restrict__ ei, int E, int n) {
    int e = blockIdx.x * blockDim.x + threadIdx.x;
    if (e < E) {
        int d = load_idx(ei, E + e);  // dst
        if ((unsigned)d < (unsigned)n) atomicAdd(&g_cnt[d], 1);
    }
}

// dinv[i] = rsqrt(deg_in + 1 self loop); also single-block exclusive scan of
// counts into g_off / g_cur (1024 threads, Hillis-Steele per 1024-tile + carry)
__global__ void __launch_bounds__(1024)
scan_kernel(int n) {
    __shared__ int sh[1024];
    __shared__ int carry;
    const int tid = threadIdx.x;
    if (tid == 0) carry = 0;
    __syncthreads();
    for (int base = 0; base < n; base += 1024) {
        int i = base + tid;
        int v = (i < n) ? g_cnt[i] : 0;
        if (i < n) g_dinv[i] = rsqrtf((float)(v + 1));
        sh[tid] = v;
        __syncthreads();
#pragma unroll
        for (int off = 1; off < 1024; off <<= 1) {
            int t = (tid >= off) ? sh[tid - off] : 0;
            __syncthreads();
            sh[tid] += t;
            __syncthreads();
        }
        int excl = sh[tid] - v;
        int c = carry;
        if (i < n) {
            g_off[i] = c + excl;
            g_cur[i] = c + excl;
        }
        int total = sh[1023];
        __syncthreads();
        if (tid == 0) carry = c + total;
        __syncthreads();
    }
    if (tid == 0) g_off[n] = carry;
}

__global__ void place_kernel(const void* __restrict__ ei, int E, int n) {
    int e = blockIdx.x * blockDim.x + threadIdx.x;
    if (e >= E) return;
    int s = load_idx(ei, e);
    int d = load_idx(ei, E + e);
    if ((unsigned)s >= (unsigned)n || (unsigned)d >= (unsigned)n) return;
    int p = atomicAdd(&g_cur[d], 1);
    g_eidx[p] = s;
}

// ---------------------------------------------------------------------------
// GEMM: y_row = (act(A_row) @ W) * dinv[row]
// LAYER==1: A = X (identity activation)
// LAYER==2: A = g_agg, act = relu(a*dinv[row] + b1[k])
// ---------------------------------------------------------------------------
template <int LAYER>
__global__ void __launch_bounds__(256)
gemm_scale_kernel(const float* __restrict__ X,
                  const float* __restrict__ W,
                  const float* __restrict__ bin,   // b1 for LAYER==2 activation
                  int M) {
    constexpr int BK = 8;
    __shared__ float As[BK][128];   // transposed A tile
    __shared__ float Bs[BK][128];

    const int tid = threadIdx.x;
    const int block_row = blockIdx.x * 128;
    const int tc = (tid % 16) * 8;       // output col base
    const int tr = (tid / 16) * 8;       // output row base (within tile)

    const int a_row = tid >> 1;
    const int a_c4  = (tid & 1) * 4;
    const int b_k   = tid >> 5;
    const int b_c4  = (tid & 31) * 4;

    const int ga_row = block_row + a_row;
    float dva = 0.0f;
    if (LAYER == 2 && ga_row < M) dva = g_dinv[ga_row];

    const float* Aptr = (LAYER == 1) ? X : (const float*)g_agg;

    float acc[8][8];
#pragma unroll
    for (int i = 0; i < 8; i++)
#pragma unroll
        for (int j = 0; j < 8; j++) acc[i][j] = 0.0f;

    for (int k0 = 0; k0 < FDIM; k0 += BK) {
        float4 av = make_float4(0.f, 0.f, 0.f, 0.f);
        if (ga_row < M)
            av = *reinterpret_cast<const float4*>(Aptr + (size_t)ga_row * FDIM + k0 + a_c4);
        if (LAYER == 2) {
            av.x = fmaxf(fmaf(av.x, dva, bin[k0 + a_c4 + 0]), 0.0f);
            av.y = fmaxf(fmaf(av.y, dva, bin[k0 + a_c4 + 1]), 0.0f);
            av.z = fmaxf(fmaf(av.z, dva, bin[k0 + a_c4 + 2]), 0.0f);
            av.w = fmaxf(fmaf(av.w, dva, bin[k0 + a_c4 + 3]), 0.0f);
        }
        As[a_c4 + 0][a_row] = av.x;
        As[a_c4 + 1][a_row] = av.y;
        As[a_c4 + 2][a_row] = av.z;
        As[a_c4 + 3][a_row] = av.w;

        *reinterpret_cast<float4*>(&Bs[b_k][b_c4]) =
            *reinterpret_cast<const float4*>(W + (size_t)(k0 + b_k) * FDIM + b_c4);

        __syncthreads();

#pragma unroll
        for (int k = 0; k < BK; k++) {
            float rm[8], rn[8];
#pragma unroll
            for (int i = 0; i < 8; i++) rm[i] = As[k][tr + i];
#pragma unroll
            for (int j = 0; j < 8; j++) rn[j] = Bs[k][tc + j];
#pragma unroll
            for (int i = 0; i < 8; i++)
#pragma unroll
                for (int j = 0; j < 8; j++) acc[i][j] = fmaf(rm[i], rn[j], acc[i][j]);
        }
        __syncthreads();
    }

    // epilogue: y = acc * dinv[row]
#pragma unroll
    for (int i = 0; i < 8; i++) {
        int r = block_row + tr + i;
        if (r < M) {
            float dv = g_dinv[r];
#pragma unroll
            for (int j = 0; j < 8; j += 4) {
                float4 v;
                v.x = acc[i][j + 0] * dv;
                v.y = acc[i][j + 1] * dv;
                v.z = acc[i][j + 2] * dv;
                v.w = acc[i][j + 3] * dv;
                *reinterpret_cast<float4*>(g_y + (size_t)r * FDIM + tc + j) = v;
            }
        }
    }
}

// ---------------------------------------------------------------------------
// CSR gather-aggregate: one warp per dst node; lane owns 4 consecutive floats.
// acc = y[d] (self loop) + sum over incoming src rows. No atomics.
// FINAL==false: store raw sum to g_agg (layer 1).
// FINAL==true : out = sigmoid(dinv[d]*acc + b2); cols >= 123 forced to 0.7.
// ---------------------------------------------------------------------------
template <bool FINAL>
__global__ void __launch_bounds__(256)
agg_kernel(const float* __restrict__ b2, float* __restrict__ out, int n) {
    int nd = (int)((blockIdx.x * blockDim.x + threadIdx.x) >> 5);
    int lane = threadIdx.x & 31;
    if (nd >= n) return;
    const int c4 = lane * 4;

    int beg = g_off[nd];
    int end = g_off[nd + 1];

    float4 acc = *reinterpret_cast<const float4*>(g_y + (size_t)nd * FDIM + c4);
    float4 acc2 = make_float4(0.f, 0.f, 0.f, 0.f);

    int j = beg;
    for (; j + 1 < end; j += 2) {   // 2-way unroll for MLP
        int s0 = g_eidx[j];
        int s1 = g_eidx[j + 1];
        float4 v0 = *reinterpret_cast<const float4*>(g_y + (size_t)s0 * FDIM + c4);
        float4 v1 = *reinterpret_cast<const float4*>(g_y + (size_t)s1 * FDIM + c4);
        acc.x += v0.x; acc.y += v0.y; acc.z += v0.z; acc.w += v0.w;
        acc2.x += v1.x; acc2.y += v1.y; acc2.z += v1.z; acc2.w += v1.w;
    }
    if (j < end) {
        int s0 = g_eidx[j];
        float4 v0 = *reinterpret_cast<const float4*>(g_y + (size_t)s0 * FDIM + c4);
        acc.x += v0.x; acc.y += v0.y; acc.z += v0.z; acc.w += v0.w;
    }
    acc.x += acc2.x; acc.y += acc2.y; acc.z += acc2.z; acc.w += acc2.w;

    if (!FINAL) {
        *reinterpret_cast<float4*>(g_agg + (size_t)nd * FDIM + c4) = acc;
    } else {
        float dv = g_dinv[nd];
        float4 b = *reinterpret_cast<const float4*>(b2 + c4);
        float4 o;
        float t;
        t = fmaf(acc.x, dv, b.x); o.x = 1.0f / (1.0f + expf(-t));
        t = fmaf(acc.y, dv, b.y); o.y = 1.0f / (1.0f + expf(-t));
        t = fmaf(acc.z, dv, b.z); o.z = 1.0f / (1.0f + expf(-t));
        t = fmaf(acc.w, dv, b.w); o.w = 1.0f / (1.0f + expf(-t));
        if (c4 + 0 >= 123) o.x = 0.7f;
        if (c4 + 1 >= 123) o.y = 0.7f;
        if (c4 + 2 >= 123) o.z = 0.7f;
        if (c4 + 3 >= 123) o.w = 0.7f;
        *reinterpret_cast<float4*>(out + (size_t)nd * FDIM + c4) = o;
    }
}

// ---------------------------------------------------------------------------
extern "C" void kernel_launch(void* const* d_in, const int* in_sizes, int n_in,
                              void* d_out, int out_size) {
    const float* x  = (const float*)d_in[0];
    const void*  ei = d_in[1];
    const float* W1 = (const float*)d_in[2];
    const float* b1 = (const float*)d_in[3];
    const float* W2 = (const float*)d_in[4];
    const float* b2 = (const float*)d_in[5];
    float* out      = (float*)d_out;

    const int N = in_sizes[0] / FDIM;
    const int E = in_sizes[1] / 2;

    // detect index dtype (reads first E int64 words: in-bounds for both dtypes)
    detect_init_kernel<<<1, 1>>>();
    detect_kernel<<<(E + 255) / 256, 256>>>(
        (const unsigned long long*)ei, E, (unsigned long long)N);

    // CSR build: histogram -> scan (also computes dinv) -> placement
    cnt_init_kernel<<<(N + 255) / 256, 256>>>(N);
    cnt_accum_kernel<<<(E + 255) / 256, 256>>>(ei, E, N);
    scan_kernel<<<1, 1024>>>(N);
    place_kernel<<<(E + 255) / 256, 256>>>(ei, E, N);

    const int gemm_blocks = (N + 127) / 128;
    const int agg_blocks  = (N + 7) / 8;   // 8 warps/block, warp per node

    // layer 1: y1 = (x@W1)*dinv; agg1 = gather-sum(y1) + self loop
    gemm_scale_kernel<1><<<gemm_blocks, 256>>>(x, W1, nullptr, N);
    agg_kernel<false><<<agg_blocks, 256>>>(nullptr, nullptr, N);

    // layer 2: h = relu(agg1*dinv + b1) fused into A load; y2 written;
    // final aggregation fuses sigmoid + bias + owner-id columns
    gemm_scale_kernel<2><<<gemm_blocks, 256>>>(nullptr, W2, b1, N);
    agg_kernel<true><<<agg_blocks, 256>>>(b2, out, N);
}

// round 9
// speedup vs baseline: 3.2792x; 1.4228x over previous
#include <cuda_runtime.h>
#include <cuda_bf16.h>
#include <cstdint>
#include <cmath>

#define NMAX 100000
#define EMAX 1600000
#define FDIM 128

// ---------------------------------------------------------------------------
// device globals (allocation-free scratch)
// ---------------------------------------------------------------------------
__device__ int   g_is64;
__device__ int   g_cnt[NMAX];
__device__ int   g_off[NMAX + 1];
__device__ int   g_cur[NMAX];
__device__ int   g_eidx[EMAX];
__device__ float g_dinv[NMAX];
__device__ float g_y[(size_t)NMAX * FDIM];
__device__ float g_agg[(size_t)NMAX * FDIM];
// pre-split W as bf16 pairs, plain [k][n/2] uint32 layout (128 x 64)
__device__ __align__(16) uint32_t g_Bhi32[8192];
__device__ __align__(16) uint32_t g_Blo32[8192];

// ---------------------------------------------------------------------------
// warp-level MMA helpers (sm_80+ ISA: safe for plain sm_103 target)
// ---------------------------------------------------------------------------
__device__ __forceinline__ uint32_t smem_to_u32(const void* p) {
    uint32_t a;
    asm("{ .reg .u64 t; cvta.to.shared.u64 t, %1; cvt.u32.u64 %0, t; }"
        : "=r"(a) : "l"(p));
    return a;
}

#define LDSM_X4(r0, r1, r2, r3, addr) \
    asm volatile("ldmatrix.sync.aligned.m8n8.x4.shared.b16 {%0,%1,%2,%3}, [%4];" \
                 : "=r"(r0), "=r"(r1), "=r"(r2), "=r"(r3) : "r"(addr))
#define LDSM_X4_T(r0, r1, r2, r3, addr) \
    asm volatile("ldmatrix.sync.aligned.m8n8.x4.trans.shared.b16 {%0,%1,%2,%3}, [%4];" \
                 : "=r"(r0), "=r"(r1), "=r"(r2), "=r"(r3) : "r"(addr))

__device__ __forceinline__ void mma16816(float* c, const uint32_t* a,
                                         const uint32_t* b) {
    asm volatile(
        "mma.sync.aligned.m16n8k16.row.col.f32.bf16.bf16.f32 "
        "{%0,%1,%2,%3}, {%4,%5,%6,%7}, {%8,%9}, {%0,%1,%2,%3};"
        : "+f"(c[0]), "+f"(c[1]), "+f"(c[2]), "+f"(c[3])
        : "r"(a[0]), "r"(a[1]), "r"(a[2]), "r"(a[3]), "r"(b[0]), "r"(b[1]));
}

// ---------------------------------------------------------------------------
// index dtype detection
// ---------------------------------------------------------------------------
__global__ void detect_init_kernel() { g_is64 = 1; }
__global__ void detect_kernel(const unsigned long long* __restrict__ ei,
                              int E, unsigned long long n) {
    int i = blockIdx.x * blockDim.x + threadIdx.x;
    if (i < E && ei[i] >= n) g_is64 = 0;
}
__device__ __forceinline__ int load_idx(const void* ei, int i) {
    if (g_is64) return (int)((const long long*)ei)[i];
    return ((const int*)ei)[i];
}

// ---------------------------------------------------------------------------
// CSR build
// ---------------------------------------------------------------------------
__global__ void cnt_init_kernel(int n) {
    int i = blockIdx.x * blockDim.x + threadIdx.x;
    if (i < n) g_cnt[i] = 0;
}
__global__ void cnt_accum_kernel(const void* __restrict__ ei, int E, int n) {
    int e = blockIdx.x * blockDim.x + threadIdx.x;
    if (e < E) {
        int d = load_idx(ei, E + e);
        if ((unsigned)d < (unsigned)n) atomicAdd(&g_cnt[d], 1);
    }
}

// single-block scan, 4 elems/thread, shfl warp scans (also computes dinv)
__global__ void __launch_bounds__(1024)
scan_kernel(int n) {
    __shared__ int wsum[32];
    __shared__ int carry_s;
    const int tid = threadIdx.x, lane = tid & 31, w = tid >> 5;
    if (tid == 0) carry_s = 0;
    __syncthreads();
    for (int base = 0; base < n; base += 4096) {
        int i0 = base + tid * 4;
        int v0 = 0, v1 = 0, v2 = 0, v3 = 0;
        if (i0 + 3 < n) {
            int4 v = *reinterpret_cast<const int4*>(g_cnt + i0);
            v0 = v.x; v1 = v.y; v2 = v.z; v3 = v.w;
        } else {
            if (i0 + 0 < n) v0 = g_cnt[i0 + 0];
            if (i0 + 1 < n) v1 = g_cnt[i0 + 1];
            if (i0 + 2 < n) v2 = g_cnt[i0 + 2];
            if (i0 + 3 < n) v3 = g_cnt[i0 + 3];
        }
        if (i0 + 0 < n) g_dinv[i0 + 0] = rsqrtf((float)(v0 + 1));
        if (i0 + 1 < n) g_dinv[i0 + 1] = rsqrtf((float)(v1 + 1));
        if (i0 + 2 < n) g_dinv[i0 + 2] = rsqrtf((float)(v2 + 1));
        if (i0 + 3 < n) g_dinv[i0 + 3] = rsqrtf((float)(v3 + 1));
        int mysum = v0 + v1 + v2 + v3;
        int s = mysum;
#pragma unroll
        for (int off = 1; off < 32; off <<= 1) {
            int t = __shfl_up_sync(0xffffffffu, s, off);
            if (lane >= off) s += t;
        }
        if (lane == 31) wsum[w] = s;
        __syncthreads();
        if (w == 0) {
            int t = wsum[lane];
#pragma unroll
            for (int off = 1; off < 32; off <<= 1) {
                int u = __shfl_up_sync(0xffffffffu, t, off);
                if (lane >= off) t += u;
            }
            wsum[lane] = t;
        }
        __syncthreads();
        int warp_excl = (w > 0) ? wsum[w - 1] : 0;
        int tb = carry_s + warp_excl + (s - mysum);
        if (i0 + 0 < n) { g_off[i0 + 0] = tb; g_cur[i0 + 0] = tb; } tb += v0;
        if (i0 + 1 < n) { g_off[i0 + 1] = tb; g_cur[i0 + 1] = tb; } tb += v1;
        if (i0 + 2 < n) { g_off[i0 + 2] = tb; g_cur[i0 + 2] = tb; } tb += v2;
        if (i0 + 3 < n) { g_off[i0 + 3] = tb; g_cur[i0 + 3] = tb; } tb += v3;
        int total = wsum[31];
        __syncthreads();
        if (tid == 0) carry_s += total;
        __syncthreads();
    }
    if (tid == 0) g_off[n] = carry_s;
}

__global__ void place_kernel(const void* __restrict__ ei, int E, int n) {
    int e = blockIdx.x * blockDim.x + threadIdx.x;
    if (e >= E) return;
    int s = load_idx(ei, e);
    int d = load_idx(ei, E + e);
    if ((unsigned)s >= (unsigned)n || (unsigned)d >= (unsigned)n) return;
    int p = atomicAdd(&g_cur[d], 1);
    g_eidx[p] = s;
}

// ---------------------------------------------------------------------------
// W prep: split W (fp32 [K=128, N=128]) into bf16 hi/lo pairs along n,
// plain [k][n/2] uint32 layout.
// ---------------------------------------------------------------------------
__global__ void __launch_bounds__(256)
prep_w_kernel(const float* __restrict__ W) {
    int j = blockIdx.x * blockDim.x + threadIdx.x;  // 0..8191
    if (j >= 8192) return;
    int k = j >> 6;
    int np = (j & 63) * 2;
    float w0 = W[(size_t)k * FDIM + np];
    float w1 = W[(size_t)k * FDIM + np + 1];
    __nv_bfloat16 h0 = __float2bfloat16(w0);
    __nv_bfloat16 h1 = __float2bfloat16(w1);
    __nv_bfloat16 l0 = __float2bfloat16(w0 - __bfloat162float(h0));
    __nv_bfloat16 l1 = __float2bfloat16(w1 - __bfloat162float(h1));
    g_Bhi32[j] = (uint32_t)__bfloat16_as_ushort(h0) |
                 ((uint32_t)__bfloat16_as_ushort(h1) << 16);
    g_Blo32[j] = (uint32_t)__bfloat16_as_ushort(l0) |
                 ((uint32_t)__bfloat16_as_ushort(l1) << 16);
}

// ---------------------------------------------------------------------------
// HMMA GEMM: y_row = (act(A_row) @ W) * dinv[row], fp32 via bf16 3-term split
// (Ahi*Bhi + Alo*Bhi + Ahi*Blo). 128x128 tile/CTA, 8 warps (4x2), K=128.
// LAYER==1: A = X; LAYER==2: A = g_agg, act = relu(a*dinv[row] + b1[k]).
// ---------------------------------------------------------------------------
#define SSTRIDE 136   // bf16 elements per smem row (128 + 8 pad)
#define SM_AH 0
#define SM_AL (128 * SSTRIDE)
#define SM_BH (2 * 128 * SSTRIDE)
#define SM_BL (3 * 128 * SSTRIDE)
#define SM_ELEMS (4 * 128 * SSTRIDE)
#define SM_BYTES (SM_ELEMS * 2)

template <int LAYER>
__global__ void __launch_bounds__(256)
gemm_mma_kernel(const float* __restrict__ X,
                const float* __restrict__ bin, int M) {
    extern __shared__ __align__(16) char smem_raw[];
    __nv_bfloat16* sm = reinterpret_cast<__nv_bfloat16*>(smem_raw);
    const uint32_t sbase = smem_to_u32(smem_raw);

    const int tid = threadIdx.x;
    const int wid = tid >> 5;
    const int lane = tid & 31;
    const int warp_m = wid & 3;       // 4 m-strips of 32 rows
    const int warp_n = wid >> 2;      // 2 n-strips of 64 cols
    const int block_row = blockIdx.x * 128;

    const float* Aptr = (LAYER == 1) ? X : (const float*)g_agg;

    // --- load A (fp32), activation, split hi/lo into padded smem -----------
#pragma unroll
    for (int i = 0; i < 16; i++) {
        int f4 = tid + i * 256;           // 4096 float4s
        int row = f4 >> 5;
        int c4 = (f4 & 31) * 4;
        int grow = block_row + row;
        float4 av = make_float4(0.f, 0.f, 0.f, 0.f);
        if (grow < M) {
            av = *reinterpret_cast<const float4*>(Aptr + (size_t)grow * FDIM + c4);
            if (LAYER == 2) {
                float dv = g_dinv[grow];
                av.x = fmaxf(fmaf(av.x, dv, bin[c4 + 0]), 0.0f);
                av.y = fmaxf(fmaf(av.y, dv, bin[c4 + 1]), 0.0f);
                av.z = fmaxf(fmaf(av.z, dv, bin[c4 + 2]), 0.0f);
                av.w = fmaxf(fmaf(av.w, dv, bin[c4 + 3]), 0.0f);
            }
        }
        __nv_bfloat16 hx = __float2bfloat16(av.x), hy = __float2bfloat16(av.y);
        __nv_bfloat16 hz = __float2bfloat16(av.z), hw = __float2bfloat16(av.w);
        __nv_bfloat16 lx = __float2bfloat16(av.x - __bfloat162float(hx));
        __nv_bfloat16 ly = __float2bfloat16(av.y - __bfloat162float(hy));
        __nv_bfloat16 lz = __float2bfloat16(av.z - __bfloat162float(hz));
        __nv_bfloat16 lw = __float2bfloat16(av.w - __bfloat162float(hw));
        uint32_t* ah = reinterpret_cast<uint32_t*>(sm + SM_AH + row * SSTRIDE + c4);
        uint32_t* al = reinterpret_cast<uint32_t*>(sm + SM_AL + row * SSTRIDE + c4);
        ah[0] = (uint32_t)__bfloat16_as_ushort(hx) | ((uint32_t)__bfloat16_as_ushort(hy) << 16);
        ah[1] = (uint32_t)__bfloat16_as_ushort(hz) | ((uint32_t)__bfloat16_as_ushort(hw) << 16);
        al[0] = (uint32_t)__bfloat16_as_ushort(lx) | ((uint32_t)__bfloat16_as_ushort(ly) << 16);
        al[1] = (uint32_t)__bfloat16_as_ushort(lz) | ((uint32_t)__bfloat16_as_ushort(lw) << 16);
    }

    // --- copy pre-split B into padded smem (uint4 = 8 bf16) ----------------
#pragma unroll
    for (int i = 0; i < 8; i++) {
        int u = tid + i * 256;            // 2048 uint4 per variant
        int row = u >> 4;
        int c8 = (u & 15) * 8;
        *reinterpret_cast<uint4*>(sm + SM_BH + row * SSTRIDE + c8) =
            *(reinterpret_cast<const uint4*>(g_Bhi32) + u);
        *reinterpret_cast<uint4*>(sm + SM_BL + row * SSTRIDE + c8) =
            *(reinterpret_cast<const uint4*>(g_Blo32) + u);
    }
    __syncthreads();

    // --- main MMA loop ------------------------------------------------------
    float acc[2][8][4];
#pragma unroll
    for (int mt = 0; mt < 2; mt++)
#pragma unroll
        for (int nt = 0; nt < 8; nt++)
#pragma unroll
            for (int q = 0; q < 4; q++) acc[mt][nt][q] = 0.0f;

    const int lrow = lane & 15;
    const int lcol = (lane >> 4) * 8;

#pragma unroll
    for (int ks = 0; ks < 8; ks++) {
        uint32_t ah[2][4], al[2][4], bf[4][4];
        // A fragments (hi and lo)
#pragma unroll
        for (int mt = 0; mt < 2; mt++) {
            int row = warp_m * 32 + mt * 16 + lrow;
            int col = ks * 16 + lcol;
            uint32_t addr_h = sbase + (uint32_t)((SM_AH + row * SSTRIDE + col) * 2);
            uint32_t addr_l = sbase + (uint32_t)((SM_AL + row * SSTRIDE + col) * 2);
            LDSM_X4(ah[mt][0], ah[mt][1], ah[mt][2], ah[mt][3], addr_h);
            LDSM_X4(al[mt][0], al[mt][1], al[mt][2], al[mt][3], addr_l);
        }
        // B hi fragments: np covers 16 cols (two n8 tiles)
#pragma unroll
        for (int np = 0; np < 4; np++) {
            int r = ks * 16 + lrow;
            int c = warp_n * 64 + np * 16 + lcol;
            uint32_t addr = sbase + (uint32_t)((SM_BH + r * SSTRIDE + c) * 2);
            LDSM_X4_T(bf[np][0], bf[np][1], bf[np][2], bf[np][3], addr);
        }
        // hi*hi + lo*hi
#pragma unroll
        for (int mt = 0; mt < 2; mt++)
#pragma unroll
            for (int np = 0; np < 4; np++) {
                mma16816(acc[mt][np * 2 + 0], ah[mt], &bf[np][0]);
                mma16816(acc[mt][np * 2 + 1], ah[mt], &bf[np][2]);
                mma16816(acc[mt][np * 2 + 0], al[mt], &bf[np][0]);
                mma16816(acc[mt][np * 2 + 1], al[mt], &bf[np][2]);
            }
        // B lo fragments, hi*lo
#pragma unroll
        for (int np = 0; np < 4; np++) {
            int r = ks * 16 + lrow;
            int c = warp_n * 64 + np * 16 + lcol;
            uint32_t addr = sbase + (uint32_t)((SM_BL + r * SSTRIDE + c) * 2);
            LDSM_X4_T(bf[np][0], bf[np][1], bf[np][2], bf[np][3], addr);
        }
#pragma unroll
        for (int mt = 0; mt < 2; mt++)
#pragma unroll
            for (int np = 0; np < 4; np++) {
                mma16816(acc[mt][np * 2 + 0], ah[mt], &bf[np][0]);
                mma16816(acc[mt][np * 2 + 1], ah[mt], &bf[np][2]);
            }
    }

    // --- epilogue: scale by dinv, store to g_y ------------------------------
    const int er0 = lane >> 2;            // 0..7
    const int ec = (lane & 3) * 2;
#pragma unroll
    for (int mt = 0; mt < 2; mt++) {
        int row0 = block_row + warp_m * 32 + mt * 16 + er0;
        int row1 = row0 + 8;
        float dv0 = (row0 < M) ? g_dinv[row0] : 0.0f;
        float dv1 = (row1 < M) ? g_dinv[row1] : 0.0f;
#pragma unroll
        for (int nt = 0; nt < 8; nt++) {
            int col = warp_n * 64 + nt * 8 + ec;
            if (row0 < M) {
                float2 v = make_float2(acc[mt][nt][0] * dv0, acc[mt][nt][1] * dv0);
                *reinterpret_cast<float2*>(g_y + (size_t)row0 * FDIM + col) = v;
            }
            if (row1 < M) {
                float2 v = make_float2(acc[mt][nt][2] * dv1, acc[mt][nt][3] * dv1);
                *reinterpret_cast<float2*>(g_y + (size_t)row1 * FDIM + col) = v;
            }
        }
    }
}

// ---------------------------------------------------------------------------
// CSR gather-aggregate (unchanged, warp per node)
// ---------------------------------------------------------------------------
template <bool FINAL>
__global__ void __launch_bounds__(256)
agg_kernel(const float* __restrict__ b2, float* __restrict__ out, int n) {
    int nd = (int)((blockIdx.x * blockDim.x + threadIdx.x) >> 5);
    int lane = threadIdx.x & 31;
    if (nd >= n) return;
    const int c4 = lane * 4;

    int beg = g_off[nd];
    int end = g_off[nd + 1];

    float4 acc = *reinterpret_cast<const float4*>(g_y + (size_t)nd * FDIM + c4);
    float4 acc2 = make_float4(0.f, 0.f, 0.f, 0.f);

    int j = beg;
    for (; j + 1 < end; j += 2) {
        int s0 = g_eidx[j];
        int s1 = g_eidx[j + 1];
        float4 v0 = *reinterpret_cast<const float4*>(g_y + (size_t)s0 * FDIM + c4);
        float4 v1 = *reinterpret_cast<const float4*>(g_y + (size_t)s1 * FDIM + c4);
        acc.x += v0.x; acc.y += v0.y; acc.z += v0.z; acc.w += v0.w;
        acc2.x += v1.x; acc2.y += v1.y; acc2.z += v1.z; acc2.w += v1.w;
    }
    if (j < end) {
        int s0 = g_eidx[j];
        float4 v0 = *reinterpret_cast<const float4*>(g_y + (size_t)s0 * FDIM + c4);
        acc.x += v0.x; acc.y += v0.y; acc.z += v0.z; acc.w += v0.w;
    }
    acc.x += acc2.x; acc.y += acc2.y; acc.z += acc2.z; acc.w += acc2.w;

    if (!FINAL) {
        *reinterpret_cast<float4*>(g_agg + (size_t)nd * FDIM + c4) = acc;
    } else {
        float dv = g_dinv[nd];
        float4 b = *reinterpret_cast<const float4*>(b2 + c4);
        float4 o;
        float t;
        t = fmaf(acc.x, dv, b.x); o.x = 1.0f / (1.0f + expf(-t));
        t = fmaf(acc.y, dv, b.y); o.y = 1.0f / (1.0f + expf(-t));
        t = fmaf(acc.z, dv, b.z); o.z = 1.0f / (1.0f + expf(-t));
        t = fmaf(acc.w, dv, b.w); o.w = 1.0f / (1.0f + expf(-t));
        if (c4 + 0 >= 123) o.x = 0.7f;
        if (c4 + 1 >= 123) o.y = 0.7f;
        if (c4 + 2 >= 123) o.z = 0.7f;
        if (c4 + 3 >= 123) o.w = 0.7f;
        *reinterpret_cast<float4*>(out + (size_t)nd * FDIM + c4) = o;
    }
}

// ---------------------------------------------------------------------------
extern "C" void kernel_launch(void* const* d_in, const int* in_sizes, int n_in,
                              void* d_out, int out_size) {
    const float* x  = (const float*)d_in[0];
    const void*  ei = d_in[1];
    const float* W1 = (const float*)d_in[2];
    const float* b1 = (const float*)d_in[3];
    const float* W2 = (const float*)d_in[4];
    const float* b2 = (const float*)d_in[5];
    float* out      = (float*)d_out;

    const int N = in_sizes[0] / FDIM;
    const int E = in_sizes[1] / 2;

    cudaFuncSetAttribute(gemm_mma_kernel<1>,
                         cudaFuncAttributeMaxDynamicSharedMemorySize, SM_BYTES);
    cudaFuncSetAttribute(gemm_mma_kernel<2>,
                         cudaFuncAttributeMaxDynamicSharedMemorySize, SM_BYTES);

    // index dtype detection
    detect_init_kernel<<<1, 1>>>();
    detect_kernel<<<(E + 255) / 256, 256>>>(
        (const unsigned long long*)ei, E, (unsigned long long)N);

    // CSR build: histogram -> scan (+dinv) -> placement
    cnt_init_kernel<<<(N + 255) / 256, 256>>>(N);
    cnt_accum_kernel<<<(E + 255) / 256, 256>>>(ei, E, N);
    scan_kernel<<<1, 1024>>>(N);
    place_kernel<<<(E + 255) / 256, 256>>>(ei, E, N);

    const int gemm_blocks = (N + 127) / 128;
    const int agg_blocks  = (N + 7) / 8;

    // layer 1
    prep_w_kernel<<<32, 256>>>(W1);
    gemm_mma_kernel<1><<<gemm_blocks, 256, SM_BYTES>>>(x, nullptr, N);
    agg_kernel<false><<<agg_blocks, 256>>>(nullptr, nullptr, N);

    // layer 2 (+ fused final epilogue)
    prep_w_kernel<<<32, 256>>>(W2);
    gemm_mma_kernel<2><<<gemm_blocks, 256, SM_BYTES>>>(nullptr, b1, N);
    agg_kernel<true><<<agg_blocks, 256>>>(b2, out, N);
}